// round 1
// baseline (speedup 1.0000x reference)
#include <cuda_runtime.h>
#include <math.h>

#define NS 4096
#define NT 4096
#define ROWS_PER_BLOCK 32

// accumulators: [0]=pde sum, [1]=bc sum, [2]=tc sum
__device__ double g_acc[3];

__global__ void init_kernel() {
    g_acc[0] = 0.0; g_acc[1] = 0.0; g_acc[2] = 0.0;
}

__global__ __launch_bounds__(256) void pde_kernel(const float* __restrict__ V,
                                                  float C1, float dL)
{
    const int tid  = threadIdx.x;
    const int lane = tid & 31;
    const int j0   = blockIdx.x * 1024 + tid * 4;   // this thread's 4-col chunk

    const int r_begin = blockIdx.y * ROWS_PER_BLOCK;
    const int i_lo = (r_begin < 1) ? 1 : r_begin;
    const int i_hi_raw = r_begin + ROWS_PER_BLOCK - 1;
    const int i_hi = (i_hi_raw > NS - 2) ? (NS - 2) : i_hi_raw;

    const float w_first = (j0 == 0)        ? 0.0f : 1.0f;   // mask j==0
    const float w_last  = (j0 + 3 == NT-1) ? 0.0f : 1.0f;   // mask j==NT-1

    const float INV2DT = 4095.0f / 0.04f;       // (N_T-1)/(2*TAU_MAX)
    const float INV2DU = 4095.0f * 0.5f;        // 1/(2*DU)
    const float INVDU2 = 4095.0f * 4095.0f;     // 1/DU^2

    // rolling 3-row register window
    float4 vm = *(const float4*)(V + (size_t)(i_lo - 1) * NT + j0);
    float4 vc = *(const float4*)(V + (size_t)i_lo       * NT + j0);

    double acc = 0.0;

    for (int i = i_lo; i <= i_hi; ++i) {
        float4 vp = *(const float4*)(V + (size_t)(i + 1) * NT + j0);

        // t-direction neighbors of the center row via lane shuffle
        float left  = __shfl_up_sync(0xffffffffu, vc.w, 1);
        float right = __shfl_down_sync(0xffffffffu, vc.x, 1);
        if (lane == 0)  left  = V[(size_t)i * NT + (j0 > 0 ? j0 - 1 : 0)];
        if (lane == 31) right = V[(size_t)i * NT + (j0 + 4 < NT ? j0 + 4 : NT - 1)];

        // stretched-grid metrics for this row (uniform across block, cheap)
        float u   = (float)i * (1.0f / 4095.0f);
        float L   = fmaf(dL, u, C1);
        float L2  = L * L;
        float S   = fmaf(30.0f, fmaf(L2 * L, (1.0f / 6.0f), L), 100.0f);
        float Sn  = S * (1.0f / 300.0f);
        float Su  = 0.1f * dL * fmaf(0.5f, L2, 1.0f);   // S_u / S_MAX
        float Suu = 0.1f * dL * dL * L;                 // S_uu / S_MAX
        float rSu = 1.0f / Su;
        float rSu2 = rSu * rSu;
        float a  = INVDU2 * rSu2;                // coeff of Duu in V_SS
        float b  = INV2DU * Suu * rSu2 * rSu;    // coeff of Du  in V_SS
        float c2 = Sn * Sn;                      // S_norm^2
        float c1 = 2.5f * Sn * INV2DU * rSu;     // ALPHA*S_norm/(S_u_n) * 1/(2DU)

        const float cL[4] = {left, vc.x, vc.y, vc.z};
        const float cC[4] = {vc.x, vc.y, vc.z, vc.w};
        const float cR[4] = {vc.y, vc.z, vc.w, right};
        const float um[4] = {vm.x, vm.y, vm.z, vm.w};
        const float up[4] = {vp.x, vp.y, vp.z, vp.w};
        const float w[4]  = {w_first, 1.0f, 1.0f, w_last};

        float rowsum = 0.0f;
        #pragma unroll
        for (int k = 0; k < 4; ++k) {
            float Du  = up[k] - um[k];
            float Duu = (up[k] + um[k]) - 2.0f * cC[k];
            float Dt  = cR[k] - cL[k];
            float VSS = fmaf(Duu, a, -Du * b);
            VSS = fminf(fmaxf(VSS, -100.0f), 100.0f);
            float r = fmaf(Dt, INV2DT, 2.5f * cC[k]);
            r = fmaf(-c2, VSS, r);
            r = fmaf(-c1, Du, r);
            float rw = r * w[k];
            rowsum = fmaf(rw, r, rowsum);
        }
        acc += (double)rowsum;

        vm = vc; vc = vp;
    }

    // warp reduce (double)
    #pragma unroll
    for (int o = 16; o > 0; o >>= 1)
        acc += __shfl_down_sync(0xffffffffu, acc, o);

    __shared__ double warpsum[8];
    if (lane == 0) warpsum[tid >> 5] = acc;
    __syncthreads();
    if (tid == 0) {
        double s = 0.0;
        #pragma unroll
        for (int k = 0; k < 8; ++k) s += warpsum[k];
        atomicAdd(&g_acc[0], s);
    }
}

__global__ __launch_bounds__(256) void bctc_kernel(const float* __restrict__ V)
{
    const int tid = threadIdx.x;
    double acc = 0.0;

    if (blockIdx.x == 0) {
        // far-field BC at S=S_max: row NS-1 over all t
        const float* rowp = V + (size_t)(NS - 1) * NT;
        for (int t = tid; t < NT; t += 256) {
            float tn = (float)t * (1.0f / 4095.0f);
            float target = 1.0f - (1.0f / 3.0f) * expf(-0.05f * (1.0f - tn));
            float d = rowp[t] - target;
            acc += (double)(d * d);
        }
    } else {
        // terminal condition at t=T: column NT-1 over all s, Huber loss
        for (int s = tid; s < NS; s += 256) {
            float u  = (float)s * (1.0f / 4095.0f);
            float x  = 50.0f * (u - (1.0f / 3.0f));
            float sp = (fmaxf(x, 0.0f) + log1pf(expf(-fabsf(x)))) * (1.0f / 50.0f);
            float d  = V[(size_t)s * NT + (NT - 1)] - sp;
            float ad = fabsf(d);
            float h  = (ad < 0.01f) ? 0.5f * d * d : 0.01f * (ad - 0.005f);
            acc += (double)h;
        }
    }

    const int lane = tid & 31;
    #pragma unroll
    for (int o = 16; o > 0; o >>= 1)
        acc += __shfl_down_sync(0xffffffffu, acc, o);

    __shared__ double warpsum[8];
    if (lane == 0) warpsum[tid >> 5] = acc;
    __syncthreads();
    if (tid == 0) {
        double s = 0.0;
        #pragma unroll
        for (int k = 0; k < 8; ++k) s += warpsum[k];
        atomicAdd(&g_acc[blockIdx.x == 0 ? 1 : 2], s);
    }
}

__global__ void fin_kernel(float* out)
{
    const double n_int = 4094.0 * 4094.0;
    double total = g_acc[0] / n_int
                 + 10.0 * (g_acc[1] / (double)NT)
                 + 10.0 * (g_acc[2] / (double)NS);
    out[0] = (float)total;
}

// Host-side: hyperbolic root of depressed cubic (CubicStretching)
static double solve_depressed_cubic(double Q)
{
    const double p = 6.0;           // CHI
    const double q = 6.0 * Q;       // CHI * Q
    double sp = sqrt(p);
    double arg = fabs(q) / (2.0 * p * sp / (3.0 * sqrt(3.0)));
    if (arg < 1.0) arg = 1.0;
    double c = 2.0 * sp * cosh(acosh(arg) / 3.0);
    return (q >= 0.0) ? -c : c;
}

extern "C" void kernel_launch(void* const* d_in, const int* in_sizes, int n_in,
                              void* d_out, int out_size)
{
    const float* V = (const float*)d_in[0];
    float* out = (float*)d_out;

    const double C1 = solve_depressed_cubic((100.0 - 0.0)   / 30.0);  // (B - 0)/ALPHA_STR
    const double C2 = solve_depressed_cubic((100.0 - 300.0) / 30.0);  // (B - S_MAX)/ALPHA_STR
    const float C1f = (float)C1;
    const float dLf = (float)(C2 - C1);

    init_kernel<<<1, 1>>>();
    dim3 grid(NT / 1024, NS / ROWS_PER_BLOCK);  // (4, 128)
    pde_kernel<<<grid, 256>>>(V, C1f, dLf);
    bctc_kernel<<<2, 256>>>(V);
    fin_kernel<<<1, 1>>>(out);
}

// round 2
// speedup vs baseline: 1.6297x; 1.6297x over previous
#include <cuda_runtime.h>
#include <math.h>

#define NS 4096
#define NT 4096
#define RPB 32
typedef unsigned long long ull;

__device__ double g_acc = 0.0;
__device__ unsigned int g_cnt = 0;

// ---- f32x2 packed helpers (sm_103a) ----
__device__ __forceinline__ ull pk2(float lo, float hi) {
    ull r; asm("mov.b64 %0,{%1,%2};" : "=l"(r) : "f"(lo), "f"(hi)); return r;
}
__device__ __forceinline__ float2 unpk2(ull v) {
    float2 f; asm("mov.b64 {%0,%1},%2;" : "=f"(f.x), "=f"(f.y) : "l"(v)); return f;
}
__device__ __forceinline__ ull fma2_(ull a, ull b, ull c) {
    ull d; asm("fma.rn.f32x2 %0,%1,%2,%3;" : "=l"(d) : "l"(a), "l"(b), "l"(c)); return d;
}
__device__ __forceinline__ ull add2_(ull a, ull b) {
    ull d; asm("add.rn.f32x2 %0,%1,%2;" : "=l"(d) : "l"(a), "l"(b)); return d;
}
__device__ __forceinline__ ull mul2_(ull a, ull b) {
    ull d; asm("mul.rn.f32x2 %0,%1,%2;" : "=l"(d) : "l"(a), "l"(b)); return d;
}

__global__ __launch_bounds__(256) void loss_kernel(const float* __restrict__ V,
                                                   float C1, float dL,
                                                   float* __restrict__ out,
                                                   unsigned int nblocks)
{
    __shared__ ulonglong2 scA[RPB];   // {a2, -b2}
    __shared__ ulonglong2 scB[RPB];   // {-c2_2, -c1_2}
    __shared__ double ws[8];

    const int tid  = threadIdx.x;
    const int lane = tid & 31;
    const int bx   = blockIdx.x;
    const int by   = blockIdx.y;
    const int j0   = bx * 1024 + tid * 4;
    const int r_begin = by * RPB;

    const float INV2DT = 4095.0f / 0.04f;   // (N_T-1)/(2*TAU_MAX)
    const float INV2DU = 4095.0f * 0.5f;
    const float INVDU2 = 4095.0f * 4095.0f;

    // per-row stretched-grid coefficients (one warp, broadcast via smem)
    if (tid < RPB) {
        int i = r_begin + tid;
        float u   = (float)i * (1.0f / 4095.0f);
        float L   = fmaf(dL, u, C1);
        float L2  = L * L;
        float S   = fmaf(30.0f, fmaf(L2 * L, (1.0f / 6.0f), L), 100.0f);
        float Sn  = S * (1.0f / 300.0f);
        float Su  = 0.1f * dL * fmaf(0.5f, L2, 1.0f);
        float Suu = 0.1f * dL * dL * L;
        float rSu  = 1.0f / Su;
        float rSu2 = rSu * rSu;
        float a  = INVDU2 * rSu2;
        float b  = INV2DU * Suu * rSu2 * rSu;
        float c2 = Sn * Sn;
        float c1 = 2.5f * Sn * INV2DU * rSu;
        scA[tid] = make_ulonglong2(pk2(a, a),    pk2(-b, -b));
        scB[tid] = make_ulonglong2(pk2(-c2, -c2), pk2(-c1, -c1));
    }
    __syncthreads();

    const int i_lo = (r_begin < 1) ? 1 : r_begin;
    const int i_hi_raw = r_begin + RPB - 1;
    const int i_hi = (i_hi_raw > NS - 2) ? (NS - 2) : i_hi_raw;

    const float w_first = (j0 == 0)          ? 0.0f : 1.0f;
    const float w_last  = (j0 + 3 == NT - 1) ? 0.0f : 1.0f;

    const ull NEG1 = pk2(-1.0f, -1.0f);
    const ull M2   = pk2(-2.0f, -2.0f);
    const ull C252 = pk2(2.5f, 2.5f);
    const ull IDT2 = pk2(INV2DT, INV2DT);
    const ull W01  = pk2(w_first, 1.0f);
    const ull W23  = pk2(1.0f, w_last);

    const float* rowptr = V + (size_t)(i_lo - 1) * NT + j0;
    float4 vm4 = *(const float4*)rowptr;
    rowptr += NT;
    float4 vc4 = *(const float4*)rowptr;

    ull um01 = pk2(vm4.x, vm4.y), um23 = pk2(vm4.z, vm4.w);
    ull cc01 = pk2(vc4.x, vc4.y), cc23 = pk2(vc4.z, vc4.w);
    ull acc0 = 0ull, acc1 = 0ull;

    for (int i = i_lo; i <= i_hi; ++i) {
        rowptr += NT;
        float4 vp4 = *(const float4*)rowptr;

        float left  = __shfl_up_sync(0xffffffffu, vc4.w, 1);
        float right = __shfl_down_sync(0xffffffffu, vc4.x, 1);
        if (lane == 0)  left  = __ldg(V + (size_t)i * NT + (j0 > 0 ? j0 - 1 : 0));
        if (lane == 31) right = __ldg(V + (size_t)i * NT + (j0 + 4 < NT ? j0 + 4 : NT - 1));

        ull up01 = pk2(vp4.x, vp4.y), up23 = pk2(vp4.z, vp4.w);
        ull cL01 = pk2(left, vc4.x);
        ull yz   = pk2(vc4.y, vc4.z);          // shared: cL23 == cR01
        ull cR23 = pk2(vc4.w, right);

        ulonglong2 cA = scA[i - r_begin];
        ulonglong2 cB = scB[i - r_begin];

        ull Du01  = fma2_(um01, NEG1, up01);
        ull Du23  = fma2_(um23, NEG1, up23);
        ull Duu01 = fma2_(cc01, M2, add2_(up01, um01));
        ull Duu23 = fma2_(cc23, M2, add2_(up23, um23));

        ull VSS01 = fma2_(Duu01, cA.x, mul2_(Du01, cA.y));
        ull VSS23 = fma2_(Duu23, cA.x, mul2_(Du23, cA.y));
        // clamp components (FMNMX, alu pipe)
        float2 t0 = unpk2(VSS01);
        t0.x = fminf(fmaxf(t0.x, -100.0f), 100.0f);
        t0.y = fminf(fmaxf(t0.y, -100.0f), 100.0f);
        VSS01 = pk2(t0.x, t0.y);
        float2 t1 = unpk2(VSS23);
        t1.x = fminf(fmaxf(t1.x, -100.0f), 100.0f);
        t1.y = fminf(fmaxf(t1.y, -100.0f), 100.0f);
        VSS23 = pk2(t1.x, t1.y);

        ull Dt01 = fma2_(cL01, NEG1, yz);
        ull Dt23 = fma2_(yz, NEG1, cR23);

        ull r01 = fma2_(Dt01, IDT2, mul2_(cc01, C252));
        r01 = fma2_(VSS01, cB.x, r01);
        r01 = fma2_(Du01,  cB.y, r01);
        ull r23 = fma2_(Dt23, IDT2, mul2_(cc23, C252));
        r23 = fma2_(VSS23, cB.x, r23);
        r23 = fma2_(Du23,  cB.y, r23);

        acc0 = fma2_(mul2_(r01, W01), r01, acc0);
        acc1 = fma2_(mul2_(r23, W23), r23, acc1);

        um01 = cc01; um23 = cc23; cc01 = up01; cc23 = up23; vc4 = vp4;
    }

    float2 a0 = unpk2(acc0), a1 = unpk2(acc1);
    double p = ((double)a0.x + (double)a0.y + (double)a1.x + (double)a1.y)
             * (1.0 / (4094.0 * 4094.0));

    // ---- BC / TC tails folded into two blocks ----
    if (by == 0 && bx == 0) {
        const float* rowp = V + (size_t)(NS - 1) * NT;
        double s = 0.0;
        for (int t = tid; t < NT; t += 256) {
            float tn = (float)t * (1.0f / 4095.0f);
            float target = 1.0f - (1.0f / 3.0f) * expf(-0.05f * (1.0f - tn));
            float d = rowp[t] - target;
            s += (double)(d * d);
        }
        p += s * (10.0 / (double)NT);
    } else if (by == 0 && bx == 1) {
        double s = 0.0;
        for (int si = tid; si < NS; si += 256) {
            float u  = (float)si * (1.0f / 4095.0f);
            float x  = 50.0f * (u - (1.0f / 3.0f));
            float sp = (fmaxf(x, 0.0f) + log1pf(expf(-fabsf(x)))) * (1.0f / 50.0f);
            float d  = V[(size_t)si * NT + (NT - 1)] - sp;
            float ad = fabsf(d);
            float h  = (ad < 0.01f) ? 0.5f * d * d : 0.01f * (ad - 0.005f);
            s += (double)h;
        }
        p += s * (10.0 / (double)NS);
    }

    // ---- block reduce (double) ----
    #pragma unroll
    for (int o = 16; o > 0; o >>= 1)
        p += __shfl_down_sync(0xffffffffu, p, o);
    if (lane == 0) ws[tid >> 5] = p;
    __syncthreads();

    if (tid == 0) {
        double s = 0.0;
        #pragma unroll
        for (int k = 0; k < 8; ++k) s += ws[k];
        atomicAdd(&g_acc, s);
        __threadfence();
        unsigned int t = atomicAdd(&g_cnt, 1u);
        if (t == nblocks - 1u) {
            double total = atomicAdd(&g_acc, 0.0);
            out[0] = (float)total;
            g_acc = 0.0;
            __threadfence();
            g_cnt = 0u;
        }
    }
}

// Host-side: hyperbolic root of depressed cubic (CubicStretching)
static double solve_depressed_cubic(double Q)
{
    const double p = 6.0;
    const double q = 6.0 * Q;
    double sp = sqrt(p);
    double arg = fabs(q) / (2.0 * p * sp / (3.0 * sqrt(3.0)));
    if (arg < 1.0) arg = 1.0;
    double c = 2.0 * sp * cosh(acosh(arg) / 3.0);
    return (q >= 0.0) ? -c : c;
}

extern "C" void kernel_launch(void* const* d_in, const int* in_sizes, int n_in,
                              void* d_out, int out_size)
{
    const float* V = (const float*)d_in[0];
    float* out = (float*)d_out;

    const double C1 = solve_depressed_cubic((100.0 - 0.0)   / 30.0);
    const double C2 = solve_depressed_cubic((100.0 - 300.0) / 30.0);
    const float C1f = (float)C1;
    const float dLf = (float)(C2 - C1);

    dim3 grid(NT / 1024, NS / RPB);   // (4, 128) = 512 blocks
    loss_kernel<<<grid, 256>>>(V, C1f, dLf, out, 512u);
}